// round 16
// baseline (speedup 1.0000x reference)
#include <cuda_runtime.h>
#include <string.h>

// RoutingLayer: capsule dynamic routing.
//   N=50000, M=32 neighbors, D=128 = K(8) x 16, max_iter=6.
// Inputs: x fp32 [N,128], neighbors int32 [N*32], max_iter (fixed 6).
// Output: u fp32 [N,128].

#define N_NODES 50000
#define M_NB    32
#define D_DIM   128
#define K_CAPS  8
#define MAX_IT  6
#define EPS_N   1e-12f
#define FULLM   0xffffffffu
#define L2E     1.44269504088896f

typedef unsigned long long u64;

// ---- f32x2 packed-math helpers (ptxas never auto-fuses FFMA2 from C++) ----
__device__ __forceinline__ u64 pack2(float a, float b) {
    u64 r; asm("mov.b64 %0,{%1,%2};" : "=l"(r) : "f"(a), "f"(b)); return r;
}
__device__ __forceinline__ float2 unpack2(u64 v) {
    float2 f; asm("mov.b64 {%0,%1},%2;" : "=f"(f.x), "=f"(f.y) : "l"(v)); return f;
}
__device__ __forceinline__ u64 fma2(u64 a, u64 b, u64 c) {
    u64 d; asm("fma.rn.f32x2 %0,%1,%2,%3;" : "=l"(d) : "l"(a), "l"(b), "l"(c)); return d;
}
__device__ __forceinline__ u64 mul2(u64 a, u64 b) {
    u64 d; asm("mul.rn.f32x2 %0,%1,%2;" : "=l"(d) : "l"(a), "l"(b)); return d;
}
__device__ __forceinline__ u64 add2(u64 a, u64 b) {
    u64 d; asm("add.rn.f32x2 %0,%1,%2;" : "=l"(d) : "l"(a), "l"(b)); return d;
}
__device__ __forceinline__ float ex2f(float x) {
    float y; asm("ex2.approx.f32 %0,%1;" : "=f"(y) : "f"(x)); return y;
}

// Scratch: per-capsule L2-normalized x.
__device__ float g_xn[(size_t)N_NODES * D_DIM];

// ---------------------------------------------------------------------------
// Kernel 1: per-capsule normalize x into g_xn (4 lanes per 16-wide capsule).
// ---------------------------------------------------------------------------
__global__ void __launch_bounds__(256) caps_normalize_kernel(const float* __restrict__ x)
{
    int c = blockIdx.x * 64 + (threadIdx.x >> 2);
    int j = threadIdx.x & 3;
    if (c >= N_NODES * K_CAPS) return;

    const float4 v = __ldg(reinterpret_cast<const float4*>(x + (size_t)c * 16 + 4 * j));
    float ss = v.x * v.x + v.y * v.y + v.z * v.z + v.w * v.w;
    ss += __shfl_xor_sync(FULLM, ss, 1);
    ss += __shfl_xor_sync(FULLM, ss, 2);
    float inv = 1.0f / fmaxf(sqrtf(ss), EPS_N);
    float4 o = make_float4(v.x * inv, v.y * inv, v.z * inv, v.w * inv);
    *reinterpret_cast<float4*>(g_xn + (size_t)c * 16 + 4 * j) = o;
}

// ---------------------------------------------------------------------------
// Kernel 2: routing. One 128-thread CTA per node, 9 CTAs/SM (regs <= 56).
//   warp w owns m {8w..8w+7}; lane owns d-slice [4l..4l+3] (z as b64 pairs).
//   Renorm folded into exp constant: e = ex2((z.v) * inv*log2e).
//   Softmax denominators via two independent 3-stage butterflies (depth 3,
//   ILP 2 — lower latency than the 4-shfl serial reduce-scatter).
//   p allgather via 384B/warp smem exchange (2 STS + 2 broadcast LDS.128).
//   Split-d reduce: warp w owns d in [32w,32w+32), one d/lane.
// ---------------------------------------------------------------------------
__global__ void __launch_bounds__(128, 9) routing_kernel(const int* __restrict__ neighbors,
                                                         float* __restrict__ out)
{
    const int n     = blockIdx.x;
    const int tid   = threadIdx.x;
    const int w     = tid >> 5;
    const int lane  = tid & 31;
    const int c     = lane & 3;          // m-slot within reduce-scatter
    const bool b0   = (lane & 1) != 0;
    const bool b1   = (lane & 2) != 0;
    const int dmine = 32 * w + lane;     // this thread's d in reduce phase

    __shared__ float part[4 * 132];      // cross-warp partials (padded rows)
    __shared__ float u_s[D_DIM];         // raw v transpose buffer
    __shared__ float pex[4 * 96];        // per-warp p exchange: [k][q], stride 12

    // hoisted pex row base for this thread: row = capsule kk = lane>>2
    float* const mypex = pex + w * 96 + (lane >> 2) * 12;

    // Warp w's 8 neighbor indices: lanes 0..7 load, distribute via shuffle.
    int r_my = 0;
    if (lane < 8) r_my = neighbors[(size_t)n * M_NB + w * 8 + lane];

    // Gather z rows as b64 pairs (zl = d[4l..4l+1], zh = d[4l+2..4l+3]).
    u64 zl[8], zh[8];
#pragma unroll
    for (int q = 0; q < 8; q++) {
        int r = __shfl_sync(FULLM, r_my, q);
        if ((unsigned)r < (unsigned)N_NODES) {
            uint4 t = __ldg(reinterpret_cast<const uint4*>(g_xn + (size_t)r * D_DIM + 4 * lane));
            ulonglong2 zz; memcpy(&zz, &t, 16);
            zl[q] = zz.x; zh[q] = zz.y;
        } else {
            zl[q] = 0ull; zh[q] = 0ull;  // padding row (index == N)
        }
    }

    const float xcs = __ldg(g_xn + (size_t)n * D_DIM + dmine);

    u64 ul, uh;   // RAW v for this lane's d-slice, packed

    // ---- iteration 0: p = 1/8 uniformly; store raw v (no renorm) ----
    {
        u64 a0 = 0ull, a1 = 0ull;
#pragma unroll
        for (int q = 0; q < 8; q++) { a0 = add2(a0, zl[q]); a1 = add2(a1, zh[q]); }
        const u64 eighth = pack2(0.125f, 0.125f);
        a0 = mul2(a0, eighth); a1 = mul2(a1, eighth);

        *reinterpret_cast<ulonglong2*>(&part[w * 132 + 4 * lane]) = make_ulonglong2(a0, a1);
        __syncthreads();

        float v = xcs;
#pragma unroll
        for (int w2 = 0; w2 < 4; w2++) v += part[w2 * 132 + dmine];
        u_s[dmine] = v;                  // raw, unnormalized
        __syncthreads();

        uint4 t = *reinterpret_cast<const uint4*>(&u_s[4 * lane]);
        ulonglong2 uu; memcpy(&uu, &t, 16);
        ul = uu.x; uh = uu.y;
    }

    // ---- iterations 1..5 ----
#pragma unroll
    for (int it = 1; it < MAX_IT; it++) {
        // per-capsule ||v||^2 -> li = rsqrt * log2e (feeds ex2 directly)
        float li;
        {
            float2 f = unpack2(fma2(ul, ul, mul2(uh, uh)));
            float ssq = f.x + f.y;
            ssq += __shfl_xor_sync(FULLM, ssq, 1);
            ssq += __shfl_xor_sync(FULLM, ssq, 2);
            li = rsqrtf(fmaxf(ssq, EPS_N * EPS_N)) * L2E;
        }

        // lane-partial raw dots (f32x2): sp[q] = z[q][4l..4l+3] . v[4l..4l+3]
        float sp[8];
#pragma unroll
        for (int q = 0; q < 8; q++) {
            float2 f = unpack2(fma2(zl[q], ul, mul2(zh[q], uh)));
            sp[q] = f.x + f.y;
        }

        // reduce-scatter over xor1: a[j] = 2-lane sum of q = 2j + b0
        float a0, a1, a2, a3;
        {
            float sd, kp;
            sd = b0 ? sp[0] : sp[1]; kp = b0 ? sp[1] : sp[0];
            a0 = kp + __shfl_xor_sync(FULLM, sd, 1);
            sd = b0 ? sp[2] : sp[3]; kp = b0 ? sp[3] : sp[2];
            a1 = kp + __shfl_xor_sync(FULLM, sd, 1);
            sd = b0 ? sp[4] : sp[5]; kp = b0 ? sp[5] : sp[4];
            a2 = kp + __shfl_xor_sync(FULLM, sd, 1);
            sd = b0 ? sp[6] : sp[7]; kp = b0 ? sp[7] : sp[6];
            a3 = kp + __shfl_xor_sync(FULLM, sd, 1);
        }
        // reduce-scatter over xor2: s_i = full 16-dot for q = 4i + c
        float s0, s1;
        {
            float sd, kp;
            sd = b1 ? a0 : a1; kp = b1 ? a1 : a0;
            s0 = kp + __shfl_xor_sync(FULLM, sd, 2);
            sd = b1 ? a2 : a3; kp = b1 ? a3 : a2;
            s1 = kp + __shfl_xor_sync(FULLM, sd, 2);
        }

        // e = 2^{ (z.v) * inv * log2e }  (renorm folded; |s*inv| <= 1)
        float e0 = ex2f(s0 * li);
        float e1 = ex2f(s1 * li);

        // softmax denominators over k: two independent depth-3 butterflies
        float t0 = e0, t1 = e1;
        t0 += __shfl_xor_sync(FULLM, t0, 4);
        t1 += __shfl_xor_sync(FULLM, t1, 4);
        t0 += __shfl_xor_sync(FULLM, t0, 8);
        t1 += __shfl_xor_sync(FULLM, t1, 8);
        t0 += __shfl_xor_sync(FULLM, t0, 16);
        t1 += __shfl_xor_sync(FULLM, t1, 16);

        // allgather p via smem: row kk holds p for q = 0..7 of this warp
        mypex[c]     = __fdividef(e0, t0);   // p[q = c,     k = kk]
        mypex[4 + c] = __fdividef(e1, t1);   // p[q = 4 + c, k = kk]
        __syncwarp();
        const float4 lo = *reinterpret_cast<const float4*>(mypex);      // p[q=0..3]
        const float4 hi = *reinterpret_cast<const float4*>(mypex + 4);  // p[q=4..7]

        // weighted accumulation (f32x2), consuming lo/hi directly
        u64 acc0 = 0ull, acc1 = 0ull;
        {
            u64 pp;
            pp = pack2(lo.x, lo.x); acc0 = fma2(zl[0], pp, acc0); acc1 = fma2(zh[0], pp, acc1);
            pp = pack2(lo.y, lo.y); acc0 = fma2(zl[1], pp, acc0); acc1 = fma2(zh[1], pp, acc1);
            pp = pack2(lo.z, lo.z); acc0 = fma2(zl[2], pp, acc0); acc1 = fma2(zh[2], pp, acc1);
            pp = pack2(lo.w, lo.w); acc0 = fma2(zl[3], pp, acc0); acc1 = fma2(zh[3], pp, acc1);
            pp = pack2(hi.x, hi.x); acc0 = fma2(zl[4], pp, acc0); acc1 = fma2(zh[4], pp, acc1);
            pp = pack2(hi.y, hi.y); acc0 = fma2(zl[5], pp, acc0); acc1 = fma2(zh[5], pp, acc1);
            pp = pack2(hi.z, hi.z); acc0 = fma2(zl[6], pp, acc0); acc1 = fma2(zh[6], pp, acc1);
            pp = pack2(hi.w, hi.w); acc0 = fma2(zl[7], pp, acc0); acc1 = fma2(zh[7], pp, acc1);
        }

        *reinterpret_cast<ulonglong2*>(&part[w * 132 + 4 * lane]) = make_ulonglong2(acc0, acc1);
        __syncthreads();

        // split-d reduce: this thread owns d = dmine
        float v = xcs;
#pragma unroll
        for (int w2 = 0; w2 < 4; w2++) v += part[w2 * 132 + dmine];

        if (it < MAX_IT - 1) {
            u_s[dmine] = v;              // raw v; normalization folded into dots
            __syncthreads();
            uint4 t = *reinterpret_cast<const uint4*>(&u_s[4 * lane]);
            ulonglong2 uu; memcpy(&uu, &t, 16);
            ul = uu.x; uh = uu.y;
        } else {
            // last iteration: reference leaves u unnormalized; write result
            out[(size_t)n * D_DIM + dmine] = v;
        }
    }
}

// ---------------------------------------------------------------------------
extern "C" void kernel_launch(void* const* d_in, const int* in_sizes, int n_in,
                              void* d_out, int out_size)
{
    const float* x   = (const float*)d_in[0];
    const int*   nb  = (const int*)d_in[1];
    float*       out = (float*)d_out;
    (void)in_sizes; (void)n_in; (void)out_size;

    int caps   = N_NODES * K_CAPS;
    int blocks = (caps + 63) / 64;
    caps_normalize_kernel<<<blocks, 256>>>(x);

    routing_kernel<<<N_NODES, 128>>>(nb, out);
}

// round 17
// speedup vs baseline: 1.0517x; 1.0517x over previous
#include <cuda_runtime.h>
#include <string.h>

// RoutingLayer: capsule dynamic routing.
//   N=50000, M=32 neighbors, D=128 = K(8) x 16, max_iter=6.
// Inputs: x fp32 [N,128], neighbors int32 [N*32], max_iter (fixed 6).
// Output: u fp32 [N,128].
//
// R17 = byte-exact revert to R14 (best measured: 193.2us). R15 (interleave +
// ex2 fold) and R16 (butterfly denominators) both regressed; at 9 CTAs/SM
// latency is hidden and the binding resources are L1 wavefronts + issue
// slots, which R14 minimizes.

#define N_NODES 50000
#define M_NB    32
#define D_DIM   128
#define K_CAPS  8
#define MAX_IT  6
#define EPS_N   1e-12f
#define FULLM   0xffffffffu

typedef unsigned long long u64;

// ---- f32x2 packed-math helpers (ptxas never auto-fuses FFMA2 from C++) ----
__device__ __forceinline__ u64 pack2(float a, float b) {
    u64 r; asm("mov.b64 %0,{%1,%2};" : "=l"(r) : "f"(a), "f"(b)); return r;
}
__device__ __forceinline__ float2 unpack2(u64 v) {
    float2 f; asm("mov.b64 {%0,%1},%2;" : "=f"(f.x), "=f"(f.y) : "l"(v)); return f;
}
__device__ __forceinline__ u64 fma2(u64 a, u64 b, u64 c) {
    u64 d; asm("fma.rn.f32x2 %0,%1,%2,%3;" : "=l"(d) : "l"(a), "l"(b), "l"(c)); return d;
}
__device__ __forceinline__ u64 mul2(u64 a, u64 b) {
    u64 d; asm("mul.rn.f32x2 %0,%1,%2;" : "=l"(d) : "l"(a), "l"(b)); return d;
}
__device__ __forceinline__ u64 add2(u64 a, u64 b) {
    u64 d; asm("add.rn.f32x2 %0,%1,%2;" : "=l"(d) : "l"(a), "l"(b)); return d;
}

// Scratch: per-capsule L2-normalized x.
__device__ float g_xn[(size_t)N_NODES * D_DIM];

// ---------------------------------------------------------------------------
// Kernel 1: per-capsule normalize x into g_xn (4 lanes per 16-wide capsule).
// ---------------------------------------------------------------------------
__global__ void __launch_bounds__(256) caps_normalize_kernel(const float* __restrict__ x)
{
    int c = blockIdx.x * 64 + (threadIdx.x >> 2);
    int j = threadIdx.x & 3;
    if (c >= N_NODES * K_CAPS) return;

    const float4 v = __ldg(reinterpret_cast<const float4*>(x + (size_t)c * 16 + 4 * j));
    float ss = v.x * v.x + v.y * v.y + v.z * v.z + v.w * v.w;
    ss += __shfl_xor_sync(FULLM, ss, 1);
    ss += __shfl_xor_sync(FULLM, ss, 2);
    float inv = 1.0f / fmaxf(sqrtf(ss), EPS_N);
    float4 o = make_float4(v.x * inv, v.y * inv, v.z * inv, v.w * inv);
    *reinterpret_cast<float4*>(g_xn + (size_t)c * 16 + 4 * j) = o;
}

// ---------------------------------------------------------------------------
// Kernel 2: routing. One 128-thread CTA per node, 9 CTAs/SM (regs <= 56).
//   warp w owns m {8w..8w+7}; lane owns d-slice [4l..4l+3] (z as b64 pairs).
//   Renormalize is FOLDED into the dot: u_s carries raw v; the p-phase
//   computes inv_k = rsqrt(||v||^2) via a lane-local v.v partial + 2-shfl
//   allreduce and scales the raw dots. Softmax denominators via a 2-value
//   reduce-scatter (4 shfl — fewer wavefronts than 6 butterflies; latency
//   is hidden at 9 warps/SMSP). p allgather via 384B/warp smem exchange.
//   Split-d reduce: warp w owns d in [32w,32w+32), one d/lane.
// ---------------------------------------------------------------------------
__global__ void __launch_bounds__(128, 9) routing_kernel(const int* __restrict__ neighbors,
                                                         float* __restrict__ out)
{
    const int n     = blockIdx.x;
    const int tid   = threadIdx.x;
    const int w     = tid >> 5;
    const int lane  = tid & 31;
    const int c     = lane & 3;          // m-slot within reduce-scatter
    const bool b0   = (lane & 1) != 0;
    const bool b1   = (lane & 2) != 0;
    const bool b2   = (lane & 4) != 0;
    const int dmine = 32 * w + lane;     // this thread's d in reduce phase

    __shared__ float part[4 * 132];      // cross-warp partials (padded rows)
    __shared__ float u_s[D_DIM];         // raw v transpose buffer
    __shared__ float pex[4 * 96];        // per-warp p exchange: [k][q], stride 12

    // hoisted pex row base for this thread: row = capsule kk = lane>>2
    float* const mypex = pex + w * 96 + (lane >> 2) * 12;

    // Warp w's 8 neighbor indices: lanes 0..7 load, distribute via shuffle.
    int r_my = 0;
    if (lane < 8) r_my = neighbors[(size_t)n * M_NB + w * 8 + lane];

    // Gather z rows as b64 pairs (zl = d[4l..4l+1], zh = d[4l+2..4l+3]).
    u64 zl[8], zh[8];
#pragma unroll
    for (int q = 0; q < 8; q++) {
        int r = __shfl_sync(FULLM, r_my, q);
        if ((unsigned)r < (unsigned)N_NODES) {
            uint4 t = __ldg(reinterpret_cast<const uint4*>(g_xn + (size_t)r * D_DIM + 4 * lane));
            ulonglong2 zz; memcpy(&zz, &t, 16);
            zl[q] = zz.x; zh[q] = zz.y;
        } else {
            zl[q] = 0ull; zh[q] = 0ull;  // padding row (index == N)
        }
    }

    const float xcs = __ldg(g_xn + (size_t)n * D_DIM + dmine);

    u64 ul, uh;   // RAW v for this lane's d-slice, packed

    // ---- iteration 0: p = 1/8 uniformly; store raw v (no renorm) ----
    {
        u64 a0 = 0ull, a1 = 0ull;
#pragma unroll
        for (int q = 0; q < 8; q++) { a0 = add2(a0, zl[q]); a1 = add2(a1, zh[q]); }
        const u64 eighth = pack2(0.125f, 0.125f);
        a0 = mul2(a0, eighth); a1 = mul2(a1, eighth);

        *reinterpret_cast<ulonglong2*>(&part[w * 132 + 4 * lane]) = make_ulonglong2(a0, a1);
        __syncthreads();

        float v = xcs;
#pragma unroll
        for (int w2 = 0; w2 < 4; w2++) v += part[w2 * 132 + dmine];
        u_s[dmine] = v;                  // raw, unnormalized
        __syncthreads();

        uint4 t = *reinterpret_cast<const uint4*>(&u_s[4 * lane]);
        ulonglong2 uu; memcpy(&uu, &t, 16);
        ul = uu.x; uh = uu.y;
    }

    // ---- iterations 1..5 ----
#pragma unroll
    for (int it = 1; it < MAX_IT; it++) {
        // per-capsule ||v||^2: lane partial + 2-shfl allreduce over 4-lane group
        float inv;
        {
            float2 f = unpack2(fma2(ul, ul, mul2(uh, uh)));
            float ssq = f.x + f.y;
            ssq += __shfl_xor_sync(FULLM, ssq, 1);
            ssq += __shfl_xor_sync(FULLM, ssq, 2);
            inv = rsqrtf(fmaxf(ssq, EPS_N * EPS_N));   // 1/max(||v||, eps)
        }

        // lane-partial raw dots (f32x2): sp[q] = z[q][4l..4l+3] . v[4l..4l+3]
        float sp[8];
#pragma unroll
        for (int q = 0; q < 8; q++) {
            float2 f = unpack2(fma2(zl[q], ul, mul2(zh[q], uh)));
            sp[q] = f.x + f.y;
        }

        // reduce-scatter over xor1: a[j] = 2-lane sum of q = 2j + b0
        float a0, a1, a2, a3;
        {
            float sd, kp;
            sd = b0 ? sp[0] : sp[1]; kp = b0 ? sp[1] : sp[0];
            a0 = kp + __shfl_xor_sync(FULLM, sd, 1);
            sd = b0 ? sp[2] : sp[3]; kp = b0 ? sp[3] : sp[2];
            a1 = kp + __shfl_xor_sync(FULLM, sd, 1);
            sd = b0 ? sp[4] : sp[5]; kp = b0 ? sp[5] : sp[4];
            a2 = kp + __shfl_xor_sync(FULLM, sd, 1);
            sd = b0 ? sp[6] : sp[7]; kp = b0 ? sp[7] : sp[6];
            a3 = kp + __shfl_xor_sync(FULLM, sd, 1);
        }
        // reduce-scatter over xor2: s_i = full 16-dot for q = 4i + c
        float s0, s1;
        {
            float sd, kp;
            sd = b1 ? a0 : a1; kp = b1 ? a1 : a0;
            s0 = kp + __shfl_xor_sync(FULLM, sd, 2);
            sd = b1 ? a2 : a3; kp = b1 ? a3 : a2;
            s1 = kp + __shfl_xor_sync(FULLM, sd, 2);
        }

        // fold the renormalize: s = (z.v) * inv_k.  |s| <= 1 -> no max-sub.
        float e0 = __expf(s0 * inv);
        float e1 = __expf(s1 * inv);

        // softmax denominators over k (8 lanes, stride 4) via 2-value RS:
        // stage xor4 scatters (t0|t1), xor8/xor16 allreduce, xor4 exchange.
        float t0, t1;
        {
            float sd = b2 ? e0 : e1;
            float kp = b2 ? e1 : e0;
            float g  = kp + __shfl_xor_sync(FULLM, sd, 4);  // partial t_{b2}
            g += __shfl_xor_sync(FULLM, g, 8);
            g += __shfl_xor_sync(FULLM, g, 16);             // full t_{b2}
            float h = __shfl_xor_sync(FULLM, g, 4);         // partner's t
            t0 = b2 ? h : g;
            t1 = b2 ? g : h;
        }

        // allgather p via smem: row kk holds p for q = 0..7 of this warp
        mypex[c]     = __fdividef(e0, t0);   // p[q = c,     k = kk]
        mypex[4 + c] = __fdividef(e1, t1);   // p[q = 4 + c, k = kk]
        __syncwarp();
        const float4 lo = *reinterpret_cast<const float4*>(mypex);      // p[q=0..3]
        const float4 hi = *reinterpret_cast<const float4*>(mypex + 4);  // p[q=4..7]

        // weighted accumulation (f32x2), consuming lo/hi directly
        u64 acc0 = 0ull, acc1 = 0ull;
        {
            u64 pp;
            pp = pack2(lo.x, lo.x); acc0 = fma2(zl[0], pp, acc0); acc1 = fma2(zh[0], pp, acc1);
            pp = pack2(lo.y, lo.y); acc0 = fma2(zl[1], pp, acc0); acc1 = fma2(zh[1], pp, acc1);
            pp = pack2(lo.z, lo.z); acc0 = fma2(zl[2], pp, acc0); acc1 = fma2(zh[2], pp, acc1);
            pp = pack2(lo.w, lo.w); acc0 = fma2(zl[3], pp, acc0); acc1 = fma2(zh[3], pp, acc1);
            pp = pack2(hi.x, hi.x); acc0 = fma2(zl[4], pp, acc0); acc1 = fma2(zh[4], pp, acc1);
            pp = pack2(hi.y, hi.y); acc0 = fma2(zl[5], pp, acc0); acc1 = fma2(zh[5], pp, acc1);
            pp = pack2(hi.z, hi.z); acc0 = fma2(zl[6], pp, acc0); acc1 = fma2(zh[6], pp, acc1);
            pp = pack2(hi.w, hi.w); acc0 = fma2(zl[7], pp, acc0); acc1 = fma2(zh[7], pp, acc1);
        }

        *reinterpret_cast<ulonglong2*>(&part[w * 132 + 4 * lane]) = make_ulonglong2(acc0, acc1);
        __syncthreads();

        // split-d reduce: this thread owns d = dmine (no renorm here anymore)
        float v = xcs;
#pragma unroll
        for (int w2 = 0; w2 < 4; w2++) v += part[w2 * 132 + dmine];

        if (it < MAX_IT - 1) {
            u_s[dmine] = v;              // raw v; normalization folded into dots
            __syncthreads();
            uint4 t = *reinterpret_cast<const uint4*>(&u_s[4 * lane]);
            ulonglong2 uu; memcpy(&uu, &t, 16);
            ul = uu.x; uh = uu.y;
        } else {
            // last iteration: reference leaves u unnormalized; write result
            out[(size_t)n * D_DIM + dmine] = v;
        }
    }
}

// ---------------------------------------------------------------------------
extern "C" void kernel_launch(void* const* d_in, const int* in_sizes, int n_in,
                              void* d_out, int out_size)
{
    const float* x   = (const float*)d_in[0];
    const int*   nb  = (const int*)d_in[1];
    float*       out = (float*)d_out;
    (void)in_sizes; (void)n_in; (void)out_size;

    int caps   = N_NODES * K_CAPS;
    int blocks = (caps + 63) / 64;
    caps_normalize_kernel<<<blocks, 256>>>(x);

    routing_kernel<<<N_NODES, 128>>>(nb, out);
}